// round 12
// baseline (speedup 1.0000x reference)
#include <cuda_runtime.h>
#include <cuda_fp16.h>
#include <cstdint>

// ============================================================================
// untied LSTM cell, GB300 — plain sm_103 target (no tcgen05 in this harness).
// fp16 mma.sync m16n8k16 + ldmatrix.x4, 3-stage cp.async pipeline.
// R12 vs R11 (131.2us): 2 CTAs/SM so chunk barriers of one CTA overlap mma of
// the other (R11 was 1 CTA/SM: tensor idled ~45% at chunk boundaries).
// CTA tile 128x128, 256 thr, warp tile 32x64 (fits 128-reg cap), TK=64,
// 3 stages x 36.9KB = 110.6KB/CTA. Next-chunk cp.async issued pre-mma.
// ============================================================================

#define B_DIM 2048
#define H_DIM 1024
#define BH (B_DIM * H_DIM)
#define HH (H_DIM * H_DIM)

__device__ __align__(16) __half g_g16 [4u * BH];    // gate pre-acts fp16 (16MB)
__device__ __align__(16) __half g_x16 [BH];         // x fp16 (4 MB)
__device__ __align__(16) __half g_hm16[4u * BH];    // h0*mask[g] fp16 (16 MB)
__device__ __align__(16) __half g_w16 [8u * HH];    // Wx[4],Wh[4] fp16 (16 MB)

// ---------------- PTX helpers ----------------------------------------------

__device__ __forceinline__ uint32_t smem_u32(const void* p) {
    uint32_t a;
    asm("{ .reg .u64 t; cvta.to.shared.u64 t, %1; cvt.u32.u64 %0, t; }"
        : "=r"(a) : "l"(p));
    return a;
}

__device__ __forceinline__ void cp_async16(void* sdst, const void* gsrc) {
    asm volatile("cp.async.cg.shared.global [%0], [%1], 16;"
                 :: "r"(smem_u32(sdst)), "l"(gsrc));
}
__device__ __forceinline__ void cp_commit() {
    asm volatile("cp.async.commit_group;" ::: "memory");
}
template <int N>
__device__ __forceinline__ void cp_wait() {
    asm volatile("cp.async.wait_group %0;" :: "n"(N) : "memory");
}

__device__ __forceinline__ void ldm_x4(uint32_t* r, uint32_t addr) {
    asm volatile("ldmatrix.sync.aligned.m8n8.x4.shared.b16 {%0,%1,%2,%3}, [%4];"
                 : "=r"(r[0]), "=r"(r[1]), "=r"(r[2]), "=r"(r[3]) : "r"(addr));
}

__device__ __forceinline__ void mma_f16(float* c, const uint32_t* a,
                                        const uint32_t* b) {
    asm volatile(
        "mma.sync.aligned.m16n8k16.row.col.f32.f16.f16.f32 "
        "{%0,%1,%2,%3}, {%4,%5,%6,%7}, {%8,%9}, {%0,%1,%2,%3};"
        : "+f"(c[0]), "+f"(c[1]), "+f"(c[2]), "+f"(c[3])
        : "r"(a[0]), "r"(a[1]), "r"(a[2]), "r"(a[3]), "r"(b[0]), "r"(b[1]));
}

__device__ __forceinline__ uint32_t pack_h2(float lo, float hi) {
    const __half2 h = __float22half2_rn(make_float2(lo, hi));
    return *(const uint32_t*)&h;
}

// ---------------- GEMM config ----------------------------------------------

static constexpr int TM = 128, TN = 128, TK = 64;
static constexpr int STAGES = 3;
static constexpr int ROW_B = 144;                   // bytes/row: 128 + 16 pad
static constexpr int A_BYTES = TM * ROW_B;          // 18432
static constexpr int B_BYTES = TN * ROW_B;          // 18432
static constexpr int STAGE_BYTES = A_BYTES + B_BYTES;       // 36864
static constexpr int SMEM_BYTES = STAGES * STAGE_BYTES;     // 110592 (x2 CTA)

// ---------------- GEMM kernel: 256 thr, 2 CTA/SM, warp tile 32x64 -----------

__global__ void __launch_bounds__(256, 2)
lstm_gemm()
{
    extern __shared__ char smc[];
    const int tid  = threadIdx.x;
    const int lane = tid & 31;
    const int wid  = tid >> 5;          // 0..7
    const int wm   = wid >> 1;          // 0..3  (M warps, 32 rows)
    const int wn   = wid & 1;           // 0..1  (N warps, 64 cols)
    const int n_tile = blockIdx.x;      // 0..7
    const int m_tile = blockIdx.y;      // 0..15
    const int gate   = blockIdx.z;      // 0..3

    const int arow0 = m_tile * TM;
    const int brow0 = n_tile * TN;
    const __half* xsrc  = g_x16;
    const __half* hsrc  = g_hm16 + (size_t)gate * BH;
    const __half* wxsrc = g_w16 + (size_t)gate * HH;
    const __half* whsrc = g_w16 + (size_t)(4 + gate) * HH;

    // 32 chunks of K=64: 0..15 from x/Wx, 16..31 from hm/Wh
    auto issue = [&](int chunk, int stage) {
        const int kc = (chunk & 15) * TK;                 // halves
        const __half* Asrc = (chunk < 16) ? xsrc : hsrc;
        const __half* Bsrc = (chunk < 16) ? wxsrc : whsrc;
        char* As = smc + stage * STAGE_BYTES;
        char* Bs = As + A_BYTES;
        #pragma unroll
        for (int r = 0; r < 4; ++r) {                     // A: 1024 x 16B
            const int pos = tid + r * 256;
            const int row = pos >> 3, c = pos & 7;
            cp_async16(As + row * ROW_B + c * 16,
                       (const char*)(Asrc + (size_t)(arow0 + row) * 1024 + kc)
                           + c * 16);
        }
        #pragma unroll
        for (int r = 0; r < 4; ++r) {                     // B: 1024 x 16B
            const int pos = tid + r * 256;
            const int row = pos >> 3, c = pos & 7;
            cp_async16(Bs + row * ROW_B + c * 16,
                       (const char*)(Bsrc + (size_t)(brow0 + row) * 1024 + kc)
                           + c * 16);
        }
    };

    float acc[2][8][4];
    #pragma unroll
    for (int i = 0; i < 2; ++i)
        #pragma unroll
        for (int j = 0; j < 8; ++j)
            #pragma unroll
            for (int k = 0; k < 4; ++k) acc[i][j][k] = 0.f;

    issue(0, 0); cp_commit();
    issue(1, 1); cp_commit();

    // ldmatrix lane offsets (bytes within a stage)
    const uint32_t a_lane =
        (uint32_t)((wm * 32 + (lane & 15)) * ROW_B + (lane >> 4) * 16);
    const uint32_t b_lane =
        (uint32_t)((wn * 64 + (lane & 7) + ((lane >> 4) << 3)) * ROW_B +
                   ((lane >> 3) & 1) * 16);
    const uint32_t sm_base = smem_u32(smc);

    for (int c = 0; c < 32; ++c) {
        cp_wait<1>();
        __syncthreads();

        // prefetch chunk c+2 into the stage freed by chunk c-1 (3-stage ring;
        // the barrier above guarantees everyone finished reading it).
        if (c + 2 < 32) issue(c + 2, (c + 2) % STAGES);
        cp_commit();

        const uint32_t stg = sm_base + (c % STAGES) * STAGE_BYTES;
        const uint32_t a_base = stg + a_lane;
        const uint32_t b_base = stg + A_BYTES + b_lane;

        #pragma unroll
        for (int ks = 0; ks < 4; ++ks) {                  // K=16 per step
            uint32_t af[2][4], bf[8][2];
            #pragma unroll
            for (int mf = 0; mf < 2; ++mf)
                ldm_x4(af[mf], a_base + mf * 16 * ROW_B + ks * 32);
            #pragma unroll
            for (int nb = 0; nb < 4; ++nb) {
                uint32_t r[4];
                ldm_x4(r, b_base + nb * 16 * ROW_B + ks * 32);
                bf[2 * nb][0] = r[0]; bf[2 * nb][1] = r[1];
                bf[2 * nb + 1][0] = r[2]; bf[2 * nb + 1][1] = r[3];
            }
            #pragma unroll
            for (int mf = 0; mf < 2; ++mf)
                #pragma unroll
                for (int nf = 0; nf < 8; ++nf)
                    mma_f16(acc[mf][nf], af[mf], bf[nf]);
        }
    }

    // epilogue: pre-activations -> fp16 scratch
    const int g = lane >> 2, t2 = (lane & 3) * 2;
    #pragma unroll
    for (int mf = 0; mf < 2; ++mf) {
        const int row = arow0 + wm * 32 + mf * 16 + g;
        __half* orow = g_g16 + ((size_t)gate * B_DIM + row) * H_DIM + brow0;
        #pragma unroll
        for (int nf = 0; nf < 8; ++nf) {
            const int col = wn * 64 + nf * 8 + t2;
            *(uint32_t*)(orow + col) =
                pack_h2(acc[mf][nf][0], acc[mf][nf][1]);
            *(uint32_t*)(orow + col + 8 * H_DIM) =
                pack_h2(acc[mf][nf][2], acc[mf][nf][3]);
        }
    }
}

// ------- fused pre-pass: x->fp16, hm[g]=h0*mask[g]->fp16, weights->fp16 -----

__global__ void __launch_bounds__(256)
prep_kernel(const float* __restrict__ x,  const float* __restrict__ h0,
            const float* __restrict__ mi, const float* __restrict__ mf,
            const float* __restrict__ mc, const float* __restrict__ mo,
            const float* __restrict__ wxi, const float* __restrict__ wxf,
            const float* __restrict__ wxc, const float* __restrict__ wxo,
            const float* __restrict__ whi, const float* __restrict__ whf,
            const float* __restrict__ whc, const float* __restrict__ who)
{
    const int bid = blockIdx.x;
    if (bid < 2048) {                               // x + hm part (BH/4 elems)
        const int i = bid * 256 + threadIdx.x;
        const float4 xv = ((const float4*)x)[i];
        ((uint2*)g_x16)[i] =
            make_uint2(pack_h2(xv.x, xv.y), pack_h2(xv.z, xv.w));
        const float4 h = ((const float4*)h0)[i];
        const float4 M[4] = { ((const float4*)mi)[i], ((const float4*)mf)[i],
                              ((const float4*)mc)[i], ((const float4*)mo)[i] };
        #pragma unroll
        for (int gate = 0; gate < 4; ++gate) {
            ((uint2*)(g_hm16 + (size_t)gate * BH))[i] =
                make_uint2(pack_h2(h.x * M[gate].x, h.y * M[gate].y),
                           pack_h2(h.z * M[gate].z, h.w * M[gate].w));
        }
    } else {                                        // weight conversion part
        const int wb = bid - 2048;                  // 0..4095
        const int m = wb >> 9;                      // matrix 0..7
        const float* src =
            m == 0 ? wxi : m == 1 ? wxf : m == 2 ? wxc : m == 3 ? wxo :
            m == 4 ? whi : m == 5 ? whf : m == 6 ? whc : who;
        const int off = ((wb & 511) * 256 + threadIdx.x) * 8;
        const float4 v0 = *(const float4*)(src + off);
        const float4 v1 = *(const float4*)(src + off + 4);
        *(uint4*)(g_w16 + (size_t)m * HH + off) =
            make_uint4(pack_h2(v0.x, v0.y), pack_h2(v0.z, v0.w),
                       pack_h2(v1.x, v1.y), pack_h2(v1.z, v1.w));
    }
}

// ---------------- pointwise LSTM epilogue -----------------------------------

__device__ __forceinline__ float sigf(float v) {
    return 1.0f / (1.0f + __expf(-v));
}

__global__ void __launch_bounds__(256)
lstm_pointwise(const float* __restrict__ c0,
               const float* __restrict__ bi, const float* __restrict__ bf,
               const float* __restrict__ bc, const float* __restrict__ bo,
               const float* __restrict__ maskC, float* __restrict__ out)
{
    const int i4 = blockIdx.x * blockDim.x + threadIdx.x;   // over BH/4
    if (i4 >= BH / 4) return;
    const int k4 = i4 & (H_DIM / 4 - 1);

    const uint2 gi = ((const uint2*)(g_g16 + 0 * (size_t)BH))[i4];
    const uint2 gf = ((const uint2*)(g_g16 + 1 * (size_t)BH))[i4];
    const uint2 gc = ((const uint2*)(g_g16 + 2 * (size_t)BH))[i4];
    const uint2 go = ((const uint2*)(g_g16 + 3 * (size_t)BH))[i4];
    const float2 GI0 = __half22float2(*(const __half2*)&gi.x);
    const float2 GI1 = __half22float2(*(const __half2*)&gi.y);
    const float2 GF0 = __half22float2(*(const __half2*)&gf.x);
    const float2 GF1 = __half22float2(*(const __half2*)&gf.y);
    const float2 GC0 = __half22float2(*(const __half2*)&gc.x);
    const float2 GC1 = __half22float2(*(const __half2*)&gc.y);
    const float2 GO0 = __half22float2(*(const __half2*)&go.x);
    const float2 GO1 = __half22float2(*(const __half2*)&go.y);

    const float4 BI = ((const float4*)bi)[k4];
    const float4 BF = ((const float4*)bf)[k4];
    const float4 BC = ((const float4*)bc)[k4];
    const float4 BO = ((const float4*)bo)[k4];
    const float4 C0 = ((const float4*)c0)[i4];
    const float4 MC = ((const float4*)maskC)[i4];

    float4 h1, c1;
#define LSTM_DO(gi_, gf_, gc_, go_, cb) { \
        const float I = sigf((gi_) + BI.cb); \
        const float F = sigf((gf_) + BF.cb); \
        const float C = tanhf((gc_) + BC.cb) * MC.cb; \
        const float O = sigf((go_) + BO.cb); \
        const float cc = F * C0.cb + I * C; \
        c1.cb = cc; h1.cb = O * tanhf(cc); (void)0; }
    LSTM_DO(GI0.x, GF0.x, GC0.x, GO0.x, x)
    LSTM_DO(GI0.y, GF0.y, GC0.y, GO0.y, y)
    LSTM_DO(GI1.x, GF1.x, GC1.x, GO1.x, z)
    LSTM_DO(GI1.y, GF1.y, GC1.y, GO1.y, w)
#undef LSTM_DO

    ((float4*)out)[i4]          = h1;   // h1 at [0, BH)
    ((float4*)out)[BH / 4 + i4] = c1;   // c1 at [BH, 2*BH)
}

// ---------------- launch ----------------------------------------------------

extern "C" void kernel_launch(void* const* d_in, const int* in_sizes, int n_in,
                              void* d_out, int out_size)
{
    const float* x     = (const float*)d_in[0];
    const float* h0    = (const float*)d_in[1];
    const float* c0    = (const float*)d_in[2];
    const float* w_xi  = (const float*)d_in[3];
    const float* w_xf  = (const float*)d_in[4];
    const float* w_xc  = (const float*)d_in[5];
    const float* w_xo  = (const float*)d_in[6];
    const float* w_hi  = (const float*)d_in[7];
    const float* w_hf  = (const float*)d_in[8];
    const float* w_hc  = (const float*)d_in[9];
    const float* w_ho  = (const float*)d_in[10];
    const float* b_i   = (const float*)d_in[11];
    const float* b_f   = (const float*)d_in[12];
    const float* b_c   = (const float*)d_in[13];
    const float* b_o   = (const float*)d_in[14];
    const float* mHI   = (const float*)d_in[15];
    const float* mHF   = (const float*)d_in[16];
    const float* mHC   = (const float*)d_in[17];
    const float* mHO   = (const float*)d_in[18];
    const float* maskC = (const float*)d_in[19];

    prep_kernel<<<2048 + 4096, 256>>>(x, h0, mHI, mHF, mHC, mHO,
                                      w_xi, w_xf, w_xc, w_xo,
                                      w_hi, w_hf, w_hc, w_ho);

    cudaFuncSetAttribute(lstm_gemm,
                         cudaFuncAttributeMaxDynamicSharedMemorySize, SMEM_BYTES);
    dim3 grid(H_DIM / TN, B_DIM / TM, 4);   // (8, 16, 4) = 512 CTAs
    lstm_gemm<<<grid, 256, SMEM_BYTES>>>();

    const int n4 = BH / 4;
    lstm_pointwise<<<(n4 + 255) / 256, 256>>>(c0, b_i, b_f, b_c, b_o, maskC,
                                              (float*)d_out);
}

// round 13
// speedup vs baseline: 1.6331x; 1.6331x over previous
#include <cuda_runtime.h>
#include <cuda_fp16.h>
#include <cstdint>

// ============================================================================
// untied LSTM cell, GB300 — plain sm_103 target (no tcgen05 in this harness).
// fp16 mma.sync m16n8k16 + ldmatrix.x4, 3-stage cp.async pipeline.
// R13 vs R12 (205us, 2nd CTA not resident): XOR-swizzled SMEM (no row pad) ->
// stage 32KB, 3 stages = 98.3KB/CTA, 2 CTAs = 196.6KB — comfortably resident.
// CTA tile 128x128, 256 thr, warp tile 32x64, TK=64. Two co-resident CTAs
// interleave chunk barriers with mma to keep the HMMA pipe fed.
// ============================================================================

#define B_DIM 2048
#define H_DIM 1024
#define BH (B_DIM * H_DIM)
#define HH (H_DIM * H_DIM)

__device__ __align__(16) __half g_g16 [4u * BH];    // gate pre-acts fp16 (16MB)
__device__ __align__(16) __half g_x16 [BH];         // x fp16 (4 MB)
__device__ __align__(16) __half g_hm16[4u * BH];    // h0*mask[g] fp16 (16 MB)
__device__ __align__(16) __half g_w16 [8u * HH];    // Wx[4],Wh[4] fp16 (16 MB)

// ---------------- PTX helpers ----------------------------------------------

__device__ __forceinline__ uint32_t smem_u32(const void* p) {
    uint32_t a;
    asm("{ .reg .u64 t; cvta.to.shared.u64 t, %1; cvt.u32.u64 %0, t; }"
        : "=r"(a) : "l"(p));
    return a;
}

__device__ __forceinline__ void cp_async16(void* sdst, const void* gsrc) {
    asm volatile("cp.async.cg.shared.global [%0], [%1], 16;"
                 :: "r"(smem_u32(sdst)), "l"(gsrc));
}
__device__ __forceinline__ void cp_commit() {
    asm volatile("cp.async.commit_group;" ::: "memory");
}
template <int N>
__device__ __forceinline__ void cp_wait() {
    asm volatile("cp.async.wait_group %0;" :: "n"(N) : "memory");
}

__device__ __forceinline__ void ldm_x4(uint32_t* r, uint32_t addr) {
    asm volatile("ldmatrix.sync.aligned.m8n8.x4.shared.b16 {%0,%1,%2,%3}, [%4];"
                 : "=r"(r[0]), "=r"(r[1]), "=r"(r[2]), "=r"(r[3]) : "r"(addr));
}

__device__ __forceinline__ void mma_f16(float* c, const uint32_t* a,
                                        const uint32_t* b) {
    asm volatile(
        "mma.sync.aligned.m16n8k16.row.col.f32.f16.f16.f32 "
        "{%0,%1,%2,%3}, {%4,%5,%6,%7}, {%8,%9}, {%0,%1,%2,%3};"
        : "+f"(c[0]), "+f"(c[1]), "+f"(c[2]), "+f"(c[3])
        : "r"(a[0]), "r"(a[1]), "r"(a[2]), "r"(a[3]), "r"(b[0]), "r"(b[1]));
}

__device__ __forceinline__ uint32_t pack_h2(float lo, float hi) {
    const __half2 h = __float22half2_rn(make_float2(lo, hi));
    return *(const uint32_t*)&h;
}

// ---------------- GEMM config ----------------------------------------------
// Rows are exactly 128B; column-block cb (0..7, 16B each) is XOR-swizzled
// with (row & 7): conflict-free for both cp.async stores and ldmatrix reads.

static constexpr int TM = 128, TN = 128, TK = 64;
static constexpr int STAGES = 3;
static constexpr int A_BYTES = TM * 128;            // 16384
static constexpr int B_BYTES = TN * 128;            // 16384
static constexpr int STAGE_BYTES = A_BYTES + B_BYTES;       // 32768
static constexpr int SMEM_BYTES = STAGES * STAGE_BYTES;     // 98304 (x2 CTA ok)

// ---------------- GEMM kernel: 256 thr, 2 CTA/SM, warp tile 32x64 -----------

__global__ void __launch_bounds__(256, 2)
lstm_gemm()
{
    extern __shared__ char smc[];
    const int tid  = threadIdx.x;
    const int lane = tid & 31;
    const int wid  = tid >> 5;          // 0..7
    const int wm   = wid >> 1;          // 0..3  (M warps, 32 rows)
    const int wn   = wid & 1;           // 0..1  (N warps, 64 cols)
    const int n_tile = blockIdx.x;      // 0..7
    const int m_tile = blockIdx.y;      // 0..15
    const int gate   = blockIdx.z;      // 0..3

    const int arow0 = m_tile * TM;
    const int brow0 = n_tile * TN;
    const __half* xsrc  = g_x16;
    const __half* hsrc  = g_hm16 + (size_t)gate * BH;
    const __half* wxsrc = g_w16 + (size_t)gate * HH;
    const __half* whsrc = g_w16 + (size_t)(4 + gate) * HH;

    // 32 chunks of K=64: 0..15 from x/Wx, 16..31 from hm/Wh
    auto issue = [&](int chunk, int stage) {
        const int kc = (chunk & 15) * TK;                 // halves
        const __half* Asrc = (chunk < 16) ? xsrc : hsrc;
        const __half* Bsrc = (chunk < 16) ? wxsrc : whsrc;
        char* As = smc + stage * STAGE_BYTES;
        char* Bs = As + A_BYTES;
        #pragma unroll
        for (int r = 0; r < 4; ++r) {                     // A: 1024 x 16B
            const int pos = tid + r * 256;
            const int row = pos >> 3, cb = pos & 7;
            cp_async16(As + row * 128 + ((cb ^ (row & 7)) << 4),
                       (const char*)(Asrc + (size_t)(arow0 + row) * 1024 + kc)
                           + cb * 16);
        }
        #pragma unroll
        for (int r = 0; r < 4; ++r) {                     // B: 1024 x 16B
            const int pos = tid + r * 256;
            const int row = pos >> 3, cb = pos & 7;
            cp_async16(Bs + row * 128 + ((cb ^ (row & 7)) << 4),
                       (const char*)(Bsrc + (size_t)(brow0 + row) * 1024 + kc)
                           + cb * 16);
        }
    };

    float acc[2][8][4];
    #pragma unroll
    for (int i = 0; i < 2; ++i)
        #pragma unroll
        for (int j = 0; j < 8; ++j)
            #pragma unroll
            for (int k = 0; k < 4; ++k) acc[i][j][k] = 0.f;

    issue(0, 0); cp_commit();
    issue(1, 1); cp_commit();

    // ldmatrix lane bases. XOR key is (lane & 7) for every fragment this lane
    // touches (all row offsets within a fragment are multiples of 8 rows).
    const int      swz_key = lane & 7;
    const uint32_t a_row   = (uint32_t)(wm * 32 + (lane & 15)) * 128;
    const int      a_cb0   = lane >> 4;                   // 0/1
    const uint32_t b_row   = (uint32_t)(wn * 64 + (lane & 7) +
                                        ((lane >> 4) << 3)) * 128;
    const int      b_cb0   = (lane >> 3) & 1;             // 0/1
    const uint32_t sm_base = smem_u32(smc);

    for (int c = 0; c < 32; ++c) {
        cp_wait<1>();
        __syncthreads();

        // prefetch chunk c+2 into the stage freed by chunk c-1
        if (c + 2 < 32) issue(c + 2, (c + 2) % STAGES);
        cp_commit();

        const uint32_t stg = sm_base + (c % STAGES) * STAGE_BYTES;
        const uint32_t a_base = stg + a_row;
        const uint32_t b_base = stg + A_BYTES + b_row;

        #pragma unroll
        for (int ks = 0; ks < 4; ++ks) {                  // K=16 per step
            const uint32_t a_sw =
                (uint32_t)(((ks * 2 + a_cb0) ^ swz_key) << 4);
            const uint32_t b_sw =
                (uint32_t)(((ks * 2 + b_cb0) ^ swz_key) << 4);
            uint32_t af[2][4], bf[8][2];
            #pragma unroll
            for (int mf = 0; mf < 2; ++mf)
                ldm_x4(af[mf], a_base + (uint32_t)(mf * 16 * 128) + a_sw);
            #pragma unroll
            for (int nb = 0; nb < 4; ++nb) {
                uint32_t r[4];
                ldm_x4(r, b_base + (uint32_t)(nb * 16 * 128) + b_sw);
                bf[2 * nb][0] = r[0]; bf[2 * nb][1] = r[1];
                bf[2 * nb + 1][0] = r[2]; bf[2 * nb + 1][1] = r[3];
            }
            #pragma unroll
            for (int mf = 0; mf < 2; ++mf)
                #pragma unroll
                for (int nf = 0; nf < 8; ++nf)
                    mma_f16(acc[mf][nf], af[mf], bf[nf]);
        }
    }

    // epilogue: pre-activations -> fp16 scratch
    const int g = lane >> 2, t2 = (lane & 3) * 2;
    #pragma unroll
    for (int mf = 0; mf < 2; ++mf) {
        const int row = arow0 + wm * 32 + mf * 16 + g;
        __half* orow = g_g16 + ((size_t)gate * B_DIM + row) * H_DIM + brow0;
        #pragma unroll
        for (int nf = 0; nf < 8; ++nf) {
            const int col = wn * 64 + nf * 8 + t2;
            *(uint32_t*)(orow + col) =
                pack_h2(acc[mf][nf][0], acc[mf][nf][1]);
            *(uint32_t*)(orow + col + 8 * H_DIM) =
                pack_h2(acc[mf][nf][2], acc[mf][nf][3]);
        }
    }
}

// ------- fused pre-pass: x->fp16, hm[g]=h0*mask[g]->fp16, weights->fp16 -----

__global__ void __launch_bounds__(256)
prep_kernel(const float* __restrict__ x,  const float* __restrict__ h0,
            const float* __restrict__ mi, const float* __restrict__ mf,
            const float* __restrict__ mc, const float* __restrict__ mo,
            const float* __restrict__ wxi, const float* __restrict__ wxf,
            const float* __restrict__ wxc, const float* __restrict__ wxo,
            const float* __restrict__ whi, const float* __restrict__ whf,
            const float* __restrict__ whc, const float* __restrict__ who)
{
    const int bid = blockIdx.x;
    if (bid < 2048) {                               // x + hm part (BH/4 elems)
        const int i = bid * 256 + threadIdx.x;
        const float4 xv = ((const float4*)x)[i];
        ((uint2*)g_x16)[i] =
            make_uint2(pack_h2(xv.x, xv.y), pack_h2(xv.z, xv.w));
        const float4 h = ((const float4*)h0)[i];
        const float4 M[4] = { ((const float4*)mi)[i], ((const float4*)mf)[i],
                              ((const float4*)mc)[i], ((const float4*)mo)[i] };
        #pragma unroll
        for (int gate = 0; gate < 4; ++gate) {
            ((uint2*)(g_hm16 + (size_t)gate * BH))[i] =
                make_uint2(pack_h2(h.x * M[gate].x, h.y * M[gate].y),
                           pack_h2(h.z * M[gate].z, h.w * M[gate].w));
        }
    } else {                                        // weight conversion part
        const int wb = bid - 2048;                  // 0..4095
        const int m = wb >> 9;                      // matrix 0..7
        const float* src =
            m == 0 ? wxi : m == 1 ? wxf : m == 2 ? wxc : m == 3 ? wxo :
            m == 4 ? whi : m == 5 ? whf : m == 6 ? whc : who;
        const int off = ((wb & 511) * 256 + threadIdx.x) * 8;
        const float4 v0 = *(const float4*)(src + off);
        const float4 v1 = *(const float4*)(src + off + 4);
        *(uint4*)(g_w16 + (size_t)m * HH + off) =
            make_uint4(pack_h2(v0.x, v0.y), pack_h2(v0.z, v0.w),
                       pack_h2(v1.x, v1.y), pack_h2(v1.z, v1.w));
    }
}

// ---------------- pointwise LSTM epilogue -----------------------------------

__device__ __forceinline__ float sigf(float v) {
    return 1.0f / (1.0f + __expf(-v));
}

__global__ void __launch_bounds__(256)
lstm_pointwise(const float* __restrict__ c0,
               const float* __restrict__ bi, const float* __restrict__ bf,
               const float* __restrict__ bc, const float* __restrict__ bo,
               const float* __restrict__ maskC, float* __restrict__ out)
{
    const int i4 = blockIdx.x * blockDim.x + threadIdx.x;   // over BH/4
    if (i4 >= BH / 4) return;
    const int k4 = i4 & (H_DIM / 4 - 1);

    const uint2 gi = ((const uint2*)(g_g16 + 0 * (size_t)BH))[i4];
    const uint2 gf = ((const uint2*)(g_g16 + 1 * (size_t)BH))[i4];
    const uint2 gc = ((const uint2*)(g_g16 + 2 * (size_t)BH))[i4];
    const uint2 go = ((const uint2*)(g_g16 + 3 * (size_t)BH))[i4];
    const float2 GI0 = __half22float2(*(const __half2*)&gi.x);
    const float2 GI1 = __half22float2(*(const __half2*)&gi.y);
    const float2 GF0 = __half22float2(*(const __half2*)&gf.x);
    const float2 GF1 = __half22float2(*(const __half2*)&gf.y);
    const float2 GC0 = __half22float2(*(const __half2*)&gc.x);
    const float2 GC1 = __half22float2(*(const __half2*)&gc.y);
    const float2 GO0 = __half22float2(*(const __half2*)&go.x);
    const float2 GO1 = __half22float2(*(const __half2*)&go.y);

    const float4 BI = ((const float4*)bi)[k4];
    const float4 BF = ((const float4*)bf)[k4];
    const float4 BC = ((const float4*)bc)[k4];
    const float4 BO = ((const float4*)bo)[k4];
    const float4 C0 = ((const float4*)c0)[i4];
    const float4 MC = ((const float4*)maskC)[i4];

    float4 h1, c1;
#define LSTM_DO(gi_, gf_, gc_, go_, cb) { \
        const float I = sigf((gi_) + BI.cb); \
        const float F = sigf((gf_) + BF.cb); \
        const float C = tanhf((gc_) + BC.cb) * MC.cb; \
        const float O = sigf((go_) + BO.cb); \
        const float cc = F * C0.cb + I * C; \
        c1.cb = cc; h1.cb = O * tanhf(cc); (void)0; }
    LSTM_DO(GI0.x, GF0.x, GC0.x, GO0.x, x)
    LSTM_DO(GI0.y, GF0.y, GC0.y, GO0.y, y)
    LSTM_DO(GI1.x, GF1.x, GC1.x, GO1.x, z)
    LSTM_DO(GI1.y, GF1.y, GC1.y, GO1.y, w)
#undef LSTM_DO

    ((float4*)out)[i4]          = h1;   // h1 at [0, BH)
    ((float4*)out)[BH / 4 + i4] = c1;   // c1 at [BH, 2*BH)
}

// ---------------- launch ----------------------------------------------------

extern "C" void kernel_launch(void* const* d_in, const int* in_sizes, int n_in,
                              void* d_out, int out_size)
{
    const float* x     = (const float*)d_in[0];
    const float* h0    = (const float*)d_in[1];
    const float* c0    = (const float*)d_in[2];
    const float* w_xi  = (const float*)d_in[3];
    const float* w_xf  = (const float*)d_in[4];
    const float* w_xc  = (const float*)d_in[5];
    const float* w_xo  = (const float*)d_in[6];
    const float* w_hi  = (const float*)d_in[7];
    const float* w_hf  = (const float*)d_in[8];
    const float* w_hc  = (const float*)d_in[9];
    const float* w_ho  = (const float*)d_in[10];
    const float* b_i   = (const float*)d_in[11];
    const float* b_f   = (const float*)d_in[12];
    const float* b_c   = (const float*)d_in[13];
    const float* b_o   = (const float*)d_in[14];
    const float* mHI   = (const float*)d_in[15];
    const float* mHF   = (const float*)d_in[16];
    const float* mHC   = (const float*)d_in[17];
    const float* mHO   = (const float*)d_in[18];
    const float* maskC = (const float*)d_in[19];

    prep_kernel<<<2048 + 4096, 256>>>(x, h0, mHI, mHF, mHC, mHO,
                                      w_xi, w_xf, w_xc, w_xo,
                                      w_hi, w_hf, w_hc, w_ho);

    cudaFuncSetAttribute(lstm_gemm,
                         cudaFuncAttributeMaxDynamicSharedMemorySize, SMEM_BYTES);
    dim3 grid(H_DIM / TN, B_DIM / TM, 4);   // (8, 16, 4) = 512 CTAs
    lstm_gemm<<<grid, 256, SMEM_BYTES>>>();

    const int n4 = BH / 4;
    lstm_pointwise<<<(n4 + 255) / 256, 256>>>(c0, b_i, b_f, b_c, b_o, maskC,
                                              (float*)d_out);
}